// round 3
// baseline (speedup 1.0000x reference)
#include <cuda_runtime.h>
#include <cuda_bf16.h>
#include <cstdint>

// Problem constants (dataset fixed: N=50000, E=800000, IN=128, H=64, C=16)
#define MAXN 50016
#define MAXE 800000
#define H 64
#define IN_F 128
#define C_OUT 16

// Scratch (device globals; 16B aligned)
__device__ __align__(16) float g_dinv[MAXN];
__device__ __align__(16) int   g_degi[MAXN];
__device__ __align__(16) int   g_fill[MAXN];
__device__ __align__(16) int   g_rowptr[MAXN + 1];
__device__ __align__(16) int   g_col[MAXE];
__device__ __align__(16) float g_hs1[MAXN * H];
__device__ __align__(16) float g_acc1[MAXN * H];
__device__ __align__(16) float g_hs2[MAXN * H];
__device__ __align__(16) float g_acc2[MAXN * H];
__device__ __align__(16) float g_A[MAXN * H];
__device__ __align__(16) float g_B[MAXN * H];

// ---------------- CSR build ----------------
__global__ void zero_kernel(int N) {
    int n = blockIdx.x * blockDim.x + threadIdx.x;
    if (n < N) { g_degi[n] = 0; g_fill[n] = 0; }
}

__global__ void count_kernel(const int* __restrict__ dst, int E) {
    int e = blockIdx.x * blockDim.x + threadIdx.x;
    if (e < E) atomicAdd(&g_degi[dst[e]], 1);
}

// single-block inclusive scan over g_degi -> g_rowptr (rowptr[0]=0)
__global__ void scan_kernel(int N) {
    __shared__ int warp_sums[32];
    __shared__ int s_carry;
    int tid = threadIdx.x;
    int lane = tid & 31, wid = tid >> 5;
    if (tid == 0) { s_carry = 0; g_rowptr[0] = 0; }
    __syncthreads();
    for (int base = 0; base < N; base += 1024) {
        int i = base + tid;
        int v = (i < N) ? g_degi[i] : 0;
        int x = v;
#pragma unroll
        for (int o = 1; o < 32; o <<= 1) {
            int y = __shfl_up_sync(0xffffffffu, x, o);
            if (lane >= o) x += y;
        }
        if (lane == 31) warp_sums[wid] = x;
        __syncthreads();
        if (wid == 0) {
            int w = warp_sums[lane];
#pragma unroll
            for (int o = 1; o < 32; o <<= 1) {
                int y = __shfl_up_sync(0xffffffffu, w, o);
                if (lane >= o) w += y;
            }
            warp_sums[lane] = w;
        }
        __syncthreads();
        int incl = x + (wid > 0 ? warp_sums[wid - 1] : 0) + s_carry;
        if (i < N) g_rowptr[i + 1] = incl;
        __syncthreads();
        if (tid == 1023) s_carry = incl;
        __syncthreads();
    }
}

__global__ void dinv_kernel(int N) {
    int n = blockIdx.x * blockDim.x + threadIdx.x;
    if (n < N) g_dinv[n] = rsqrtf((float)(g_degi[n] + 1));  // +1 self loop
}

__global__ void fill_kernel(const int* __restrict__ src, const int* __restrict__ dst, int E) {
    int e = blockIdx.x * blockDim.x + threadIdx.x;
    if (e >= E) return;
    int d = dst[e];
    int pos = g_rowptr[d] + atomicAdd(&g_fill[d], 1);
    g_col[pos] = src[e];
}

// ---------------- gather: out[n] = hs[n] + sum_{s in row(n)} hs[s]
__global__ void gather_kernel(const float* __restrict__ hs, float* __restrict__ out, int N) {
    int t = blockIdx.x * blockDim.x + threadIdx.x;
    int n = t >> 4;
    if (n >= N) return;
    int c = (t & 15) << 2;
    const float* hp = hs + c;
    float4 acc = *reinterpret_cast<const float4*>(hp + (size_t)n * H);  // self loop
    int beg = g_rowptr[n], end = g_rowptr[n + 1];
    for (int i = beg; i < end; i++) {
        int s = __ldg(&g_col[i]);
        float4 v = *reinterpret_cast<const float4*>(hp + (size_t)s * H);
        acc.x += v.x; acc.y += v.y; acc.z += v.z; acc.w += v.w;
    }
    *reinterpret_cast<float4*>(out + (size_t)n * H + c) = acc;
}

// =====================================================================
// Tiled GEMM kernels: M-tile=64, N-tile=64, 256 threads, 4x4 microtile
// =====================================================================

// conv1: hs1 = (x @ W1) * dinv   (K = 128)
__global__ __launch_bounds__(256) void gemm1_tiled(
    const float* __restrict__ x, const float* __restrict__ W1, int N) {
    __shared__ float As[64][68];
    __shared__ float Ws[64][68];
    const int tx = threadIdx.x, ty = threadIdx.y;
    const int t = ty * 16 + tx;
    const int lm = t >> 4;
    const int lk4 = (t & 15) * 4;
    const int m0 = blockIdx.x * 64;

    float acc[4][4];
#pragma unroll
    for (int i = 0; i < 4; i++)
#pragma unroll
        for (int j = 0; j < 4; j++) acc[i][j] = 0.f;

    for (int k0 = 0; k0 < IN_F; k0 += 64) {
        __syncthreads();
#pragma unroll
        for (int i = 0; i < 4; i++) {
            int m = lm + 16 * i;
            int gm = m0 + m;
            float4 v = make_float4(0.f, 0.f, 0.f, 0.f);
            if (gm < N) v = *reinterpret_cast<const float4*>(x + (size_t)gm * IN_F + k0 + lk4);
            *reinterpret_cast<float4*>(&As[m][lk4]) = v;
            int k = lm + 16 * i;
            float4 w = *reinterpret_cast<const float4*>(W1 + (size_t)(k0 + k) * H + lk4);
            *reinterpret_cast<float4*>(&Ws[k][lk4]) = w;
        }
        __syncthreads();
#pragma unroll 8
        for (int kk = 0; kk < 64; kk++) {
            float4 b4 = *reinterpret_cast<const float4*>(&Ws[kk][tx * 4]);
            float a0 = As[ty * 4 + 0][kk];
            float a1 = As[ty * 4 + 1][kk];
            float a2 = As[ty * 4 + 2][kk];
            float a3 = As[ty * 4 + 3][kk];
            acc[0][0] += a0 * b4.x; acc[0][1] += a0 * b4.y; acc[0][2] += a0 * b4.z; acc[0][3] += a0 * b4.w;
            acc[1][0] += a1 * b4.x; acc[1][1] += a1 * b4.y; acc[1][2] += a1 * b4.z; acc[1][3] += a1 * b4.w;
            acc[2][0] += a2 * b4.x; acc[2][1] += a2 * b4.y; acc[2][2] += a2 * b4.z; acc[2][3] += a2 * b4.w;
            acc[3][0] += a3 * b4.x; acc[3][1] += a3 * b4.y; acc[3][2] += a3 * b4.z; acc[3][3] += a3 * b4.w;
        }
    }

#pragma unroll
    for (int i = 0; i < 4; i++) {
        int gm = m0 + ty * 4 + i;
        if (gm < N) {
            float di = g_dinv[gm];
            float4 r = make_float4(acc[i][0] * di, acc[i][1] * di, acc[i][2] * di, acc[i][3] * di);
            *reinterpret_cast<float4*>(&g_hs1[(size_t)gm * H + tx * 4]) = r;
        }
    }
}

// conv2: h1 = relu(acc1*dinv + b1); hs2 = (h1 @ W2) * dinv  (K=64)
__global__ __launch_bounds__(256) void gemm2_tiled(
    const float* __restrict__ W2, const float* __restrict__ b1, int N) {
    __shared__ float As[64][68];
    __shared__ float Ws[64][68];
    const int tx = threadIdx.x, ty = threadIdx.y;
    const int t = ty * 16 + tx;
    const int lm = t >> 4;
    const int lk4 = (t & 15) * 4;
    const int m0 = blockIdx.x * 64;

    float4 bb = *reinterpret_cast<const float4*>(b1 + lk4);
#pragma unroll
    for (int i = 0; i < 4; i++) {
        int m = lm + 16 * i;
        int gm = m0 + m;
        float4 v = make_float4(0.f, 0.f, 0.f, 0.f);
        if (gm < N) {
            float di = g_dinv[gm];
            float4 a = *reinterpret_cast<const float4*>(&g_acc1[(size_t)gm * H + lk4]);
            v.x = fmaxf(a.x * di + bb.x, 0.f);
            v.y = fmaxf(a.y * di + bb.y, 0.f);
            v.z = fmaxf(a.z * di + bb.z, 0.f);
            v.w = fmaxf(a.w * di + bb.w, 0.f);
        }
        *reinterpret_cast<float4*>(&As[m][lk4]) = v;
        int k = lm + 16 * i;
        float4 w = *reinterpret_cast<const float4*>(W2 + (size_t)k * H + lk4);
        *reinterpret_cast<float4*>(&Ws[k][lk4]) = w;
    }
    __syncthreads();

    float acc[4][4];
#pragma unroll
    for (int i = 0; i < 4; i++)
#pragma unroll
        for (int j = 0; j < 4; j++) acc[i][j] = 0.f;

#pragma unroll 8
    for (int kk = 0; kk < 64; kk++) {
        float4 b4 = *reinterpret_cast<const float4*>(&Ws[kk][tx * 4]);
        float a0 = As[ty * 4 + 0][kk];
        float a1 = As[ty * 4 + 1][kk];
        float a2 = As[ty * 4 + 2][kk];
        float a3 = As[ty * 4 + 3][kk];
        acc[0][0] += a0 * b4.x; acc[0][1] += a0 * b4.y; acc[0][2] += a0 * b4.z; acc[0][3] += a0 * b4.w;
        acc[1][0] += a1 * b4.x; acc[1][1] += a1 * b4.y; acc[1][2] += a1 * b4.z; acc[1][3] += a1 * b4.w;
        acc[2][0] += a2 * b4.x; acc[2][1] += a2 * b4.y; acc[2][2] += a2 * b4.z; acc[2][3] += a2 * b4.w;
        acc[3][0] += a3 * b4.x; acc[3][1] += a3 * b4.y; acc[3][2] += a3 * b4.z; acc[3][3] += a3 * b4.w;
    }

#pragma unroll
    for (int i = 0; i < 4; i++) {
        int gm = m0 + ty * 4 + i;
        if (gm < N) {
            float di = g_dinv[gm];
            float4 r = make_float4(acc[i][0] * di, acc[i][1] * di, acc[i][2] * di, acc[i][3] * di);
            *reinterpret_cast<float4*>(&g_hs2[(size_t)gm * H + tx * 4]) = r;
        }
    }
}

// node MLP precompute: h2 = relu(acc2*dinv + b2)
// half=0: g_A = h2 @ Wm1[0:64] + bm1 ; half=1: g_B = h2 @ Wm1[64:128]
__global__ __launch_bounds__(256) void gemm3_tiled(
    const float* __restrict__ Wm1, const float* __restrict__ b2,
    const float* __restrict__ bm1, int N) {
    __shared__ float As[64][68];
    __shared__ float Ws[64][68];
    const int tx = threadIdx.x, ty = threadIdx.y;
    const int t = ty * 16 + tx;
    const int lm = t >> 4;
    const int lk4 = (t & 15) * 4;
    const int m0 = blockIdx.x * 64;
    const int half = blockIdx.y;

    float4 bb = *reinterpret_cast<const float4*>(b2 + lk4);
#pragma unroll
    for (int i = 0; i < 4; i++) {
        int m = lm + 16 * i;
        int gm = m0 + m;
        float4 v = make_float4(0.f, 0.f, 0.f, 0.f);
        if (gm < N) {
            float di = g_dinv[gm];
            float4 a = *reinterpret_cast<const float4*>(&g_acc2[(size_t)gm * H + lk4]);
            v.x = fmaxf(a.x * di + bb.x, 0.f);
            v.y = fmaxf(a.y * di + bb.y, 0.f);
            v.z = fmaxf(a.z * di + bb.z, 0.f);
            v.w = fmaxf(a.w * di + bb.w, 0.f);
        }
        *reinterpret_cast<float4*>(&As[m][lk4]) = v;
        int k = lm + 16 * i;
        float4 w = *reinterpret_cast<const float4*>(Wm1 + (size_t)(half * H + k) * H + lk4);
        *reinterpret_cast<float4*>(&Ws[k][lk4]) = w;
    }
    __syncthreads();

    float acc[4][4];
#pragma unroll
    for (int i = 0; i < 4; i++)
#pragma unroll
        for (int j = 0; j < 4; j++) acc[i][j] = 0.f;

#pragma unroll 8
    for (int kk = 0; kk < 64; kk++) {
        float4 b4 = *reinterpret_cast<const float4*>(&Ws[kk][tx * 4]);
        float a0 = As[ty * 4 + 0][kk];
        float a1 = As[ty * 4 + 1][kk];
        float a2 = As[ty * 4 + 2][kk];
        float a3 = As[ty * 4 + 3][kk];
        acc[0][0] += a0 * b4.x; acc[0][1] += a0 * b4.y; acc[0][2] += a0 * b4.z; acc[0][3] += a0 * b4.w;
        acc[1][0] += a1 * b4.x; acc[1][1] += a1 * b4.y; acc[1][2] += a1 * b4.z; acc[1][3] += a1 * b4.w;
        acc[2][0] += a2 * b4.x; acc[2][1] += a2 * b4.y; acc[2][2] += a2 * b4.z; acc[2][3] += a2 * b4.w;
        acc[3][0] += a3 * b4.x; acc[3][1] += a3 * b4.y; acc[3][2] += a3 * b4.z; acc[3][3] += a3 * b4.w;
    }

    float4 badd = make_float4(0.f, 0.f, 0.f, 0.f);
    if (half == 0) badd = *reinterpret_cast<const float4*>(bm1 + tx * 4);
    float* outbuf = (half == 0) ? g_A : g_B;
#pragma unroll
    for (int i = 0; i < 4; i++) {
        int gm = m0 + ty * 4 + i;
        if (gm < N) {
            float4 r = make_float4(acc[i][0] + badd.x, acc[i][1] + badd.y,
                                   acc[i][2] + badd.z, acc[i][3] + badd.w);
            *reinterpret_cast<float4*>(&outbuf[(size_t)gm * H + tx * 4]) = r;
        }
    }
}

// ---------------- edge MLP: out[e] = relu(A[src]+B[dst]) @ Wm2 + bm2
__global__ void edge_kernel(const int* __restrict__ src, const int* __restrict__ dst,
                            const float* __restrict__ Wm2, const float* __restrict__ bm2,
                            float* __restrict__ out, int E) {
    __shared__ float Ws[H * C_OUT];
    __shared__ float bs[C_OUT];
    int tid = threadIdx.x;
    for (int i = tid; i < H * C_OUT; i += blockDim.x) Ws[i] = Wm2[i];
    if (tid < C_OUT) bs[tid] = bm2[tid];
    __syncthreads();

    int e = blockIdx.x * blockDim.x + tid;
    if (e >= E) return;
    int s = src[e], d = dst[e];
    const float4* Ap = reinterpret_cast<const float4*>(g_A + (size_t)s * H);
    const float4* Bp = reinterpret_cast<const float4*>(g_B + (size_t)d * H);

    float acc[C_OUT];
#pragma unroll
    for (int c = 0; c < C_OUT; c++) acc[c] = bs[c];

#pragma unroll
    for (int q = 0; q < H / 4; q++) {
        float4 a4 = Ap[q];
        float4 b4 = Bp[q];
        float z0 = fmaxf(a4.x + b4.x, 0.f);
        float z1 = fmaxf(a4.y + b4.y, 0.f);
        float z2 = fmaxf(a4.z + b4.z, 0.f);
        float z3 = fmaxf(a4.w + b4.w, 0.f);
        int k = q * 4;
        const float4* w0 = reinterpret_cast<const float4*>(Ws + (k + 0) * C_OUT);
        const float4* w1 = reinterpret_cast<const float4*>(Ws + (k + 1) * C_OUT);
        const float4* w2 = reinterpret_cast<const float4*>(Ws + (k + 2) * C_OUT);
        const float4* w3 = reinterpret_cast<const float4*>(Ws + (k + 3) * C_OUT);
#pragma unroll
        for (int cq = 0; cq < 4; cq++) {
            float4 r0 = w0[cq], r1 = w1[cq], r2 = w2[cq], r3 = w3[cq];
            acc[cq * 4 + 0] += z0 * r0.x + z1 * r1.x + z2 * r2.x + z3 * r3.x;
            acc[cq * 4 + 1] += z0 * r0.y + z1 * r1.y + z2 * r2.y + z3 * r3.y;
            acc[cq * 4 + 2] += z0 * r0.z + z1 * r1.z + z2 * r2.z + z3 * r3.z;
            acc[cq * 4 + 3] += z0 * r0.w + z1 * r1.w + z2 * r2.w + z3 * r3.w;
        }
    }

    float4* op = reinterpret_cast<float4*>(out + (size_t)e * C_OUT);
#pragma unroll
    for (int c = 0; c < 4; c++)
        op[c] = make_float4(acc[c * 4 + 0], acc[c * 4 + 1], acc[c * 4 + 2], acc[c * 4 + 3]);
}

extern "C" void kernel_launch(void* const* d_in, const int* in_sizes, int n_in,
                              void* d_out, int out_size) {
    const float* x    = (const float*)d_in[0];
    const int*   ei   = (const int*)d_in[1];
    const float* W1   = (const float*)d_in[2];
    const float* b1   = (const float*)d_in[3];
    const float* W2   = (const float*)d_in[4];
    const float* b2   = (const float*)d_in[5];
    const float* Wm1  = (const float*)d_in[6];
    const float* bm1  = (const float*)d_in[7];
    const float* Wm2  = (const float*)d_in[8];
    const float* bm2  = (const float*)d_in[9];
    float* out = (float*)d_out;

    int N = in_sizes[0] / IN_F;
    int E = in_sizes[1] / 2;
    const int* src = ei;
    const int* dst = ei + E;

    float* hs1;  cudaGetSymbolAddress((void**)&hs1,  g_hs1);
    float* acc1; cudaGetSymbolAddress((void**)&acc1, g_acc1);
    float* hs2;  cudaGetSymbolAddress((void**)&hs2,  g_hs2);
    float* acc2; cudaGetSymbolAddress((void**)&acc2, g_acc2);

    int blocks_m = (N + 63) / 64;

    // CSR build (by destination) + degrees
    zero_kernel<<<(N + 255) / 256, 256>>>(N);
    count_kernel<<<(E + 255) / 256, 256>>>(dst, E);
    scan_kernel<<<1, 1024>>>(N);
    dinv_kernel<<<(N + 255) / 256, 256>>>(N);
    fill_kernel<<<(E + 255) / 256, 256>>>(src, dst, E);

    // conv1
    gemm1_tiled<<<blocks_m, dim3(16, 16)>>>(x, W1, N);
    gather_kernel<<<(N * 16 + 255) / 256, 256>>>(hs1, acc1, N);

    // conv2
    gemm2_tiled<<<blocks_m, dim3(16, 16)>>>(W2, b1, N);
    gather_kernel<<<(N * 16 + 255) / 256, 256>>>(hs2, acc2, N);

    // node-side MLP precompute
    gemm3_tiled<<<dim3(blocks_m, 2), dim3(16, 16)>>>(Wm1, b2, bm1, N);

    // edge MLP
    edge_kernel<<<(E + 255) / 256, 256>>>(src, dst, Wm2, bm2, out, E);
}

// round 4
// speedup vs baseline: 1.3927x; 1.3927x over previous
#include <cuda_runtime.h>
#include <cuda_bf16.h>
#include <cstdint>

// Problem constants (dataset fixed: N=50000, E=800000, IN=128, H=64, C=16)
#define MAXN 50016
#define H 64
#define IN_F 128
#define C_OUT 16

// Scratch (device globals; 16B aligned)
__device__ __align__(16) int   g_degi[MAXN];
__device__ __align__(16) float g_dinv[MAXN];
__device__ __align__(16) float g_hs1[MAXN * H];
__device__ __align__(16) float g_acc1[MAXN * H];
__device__ __align__(16) float g_hs2[MAXN * H];
__device__ __align__(16) float g_acc2[MAXN * H];
__device__ __align__(16) float g_A[MAXN * H];
__device__ __align__(16) float g_B[MAXN * H];

// ---------------- degree count (int atomics; g_degi pre-zeroed by memset)
__global__ void count_kernel(const int* __restrict__ dst, int E) {
    int e = blockIdx.x * blockDim.x + threadIdx.x;
    if (e < E) atomicAdd(&g_degi[dst[e]], 1);
}

// =====================================================================
// Tiled GEMM kernels: M-tile=64, N-tile=64, 256 threads, 4x4 microtile
// =====================================================================

// conv1: hs1 = (x @ W1) * dinv ; acc1 = hs1 (self-loop seed); also writes g_dinv
__global__ __launch_bounds__(256) void gemm1_tiled(
    const float* __restrict__ x, const float* __restrict__ W1, int N) {
    __shared__ float As[64][68];
    __shared__ float Ws[64][68];
    const int tx = threadIdx.x, ty = threadIdx.y;
    const int t = ty * 16 + tx;
    const int lm = t >> 4;
    const int lk4 = (t & 15) * 4;
    const int m0 = blockIdx.x * 64;

    float acc[4][4];
#pragma unroll
    for (int i = 0; i < 4; i++)
#pragma unroll
        for (int j = 0; j < 4; j++) acc[i][j] = 0.f;

    for (int k0 = 0; k0 < IN_F; k0 += 64) {
        __syncthreads();
#pragma unroll
        for (int i = 0; i < 4; i++) {
            int m = lm + 16 * i;
            int gm = m0 + m;
            float4 v = make_float4(0.f, 0.f, 0.f, 0.f);
            if (gm < N) v = *reinterpret_cast<const float4*>(x + (size_t)gm * IN_F + k0 + lk4);
            *reinterpret_cast<float4*>(&As[m][lk4]) = v;
            int k = lm + 16 * i;
            float4 w = *reinterpret_cast<const float4*>(W1 + (size_t)(k0 + k) * H + lk4);
            *reinterpret_cast<float4*>(&Ws[k][lk4]) = w;
        }
        __syncthreads();
#pragma unroll 8
        for (int kk = 0; kk < 64; kk++) {
            float4 b4 = *reinterpret_cast<const float4*>(&Ws[kk][tx * 4]);
            float a0 = As[ty * 4 + 0][kk];
            float a1 = As[ty * 4 + 1][kk];
            float a2 = As[ty * 4 + 2][kk];
            float a3 = As[ty * 4 + 3][kk];
            acc[0][0] += a0 * b4.x; acc[0][1] += a0 * b4.y; acc[0][2] += a0 * b4.z; acc[0][3] += a0 * b4.w;
            acc[1][0] += a1 * b4.x; acc[1][1] += a1 * b4.y; acc[1][2] += a1 * b4.z; acc[1][3] += a1 * b4.w;
            acc[2][0] += a2 * b4.x; acc[2][1] += a2 * b4.y; acc[2][2] += a2 * b4.z; acc[2][3] += a2 * b4.w;
            acc[3][0] += a3 * b4.x; acc[3][1] += a3 * b4.y; acc[3][2] += a3 * b4.z; acc[3][3] += a3 * b4.w;
        }
    }

#pragma unroll
    for (int i = 0; i < 4; i++) {
        int gm = m0 + ty * 4 + i;
        if (gm < N) {
            float di = rsqrtf((float)(g_degi[gm] + 1));  // +1 self loop
            if (tx == 0) g_dinv[gm] = di;
            float4 r = make_float4(acc[i][0] * di, acc[i][1] * di, acc[i][2] * di, acc[i][3] * di);
            *reinterpret_cast<float4*>(&g_hs1[(size_t)gm * H + tx * 4]) = r;
            *reinterpret_cast<float4*>(&g_acc1[(size_t)gm * H + tx * 4]) = r;
        }
    }
}

// conv2: h1 = relu(acc1*dinv + b1); hs2 = (h1 @ W2) * dinv; acc2 = hs2 (K=64)
__global__ __launch_bounds__(256) void gemm2_tiled(
    const float* __restrict__ W2, const float* __restrict__ b1, int N) {
    __shared__ float As[64][68];
    __shared__ float Ws[64][68];
    const int tx = threadIdx.x, ty = threadIdx.y;
    const int t = ty * 16 + tx;
    const int lm = t >> 4;
    const int lk4 = (t & 15) * 4;
    const int m0 = blockIdx.x * 64;

    float4 bb = *reinterpret_cast<const float4*>(b1 + lk4);
#pragma unroll
    for (int i = 0; i < 4; i++) {
        int m = lm + 16 * i;
        int gm = m0 + m;
        float4 v = make_float4(0.f, 0.f, 0.f, 0.f);
        if (gm < N) {
            float di = g_dinv[gm];
            float4 a = *reinterpret_cast<const float4*>(&g_acc1[(size_t)gm * H + lk4]);
            v.x = fmaxf(a.x * di + bb.x, 0.f);
            v.y = fmaxf(a.y * di + bb.y, 0.f);
            v.z = fmaxf(a.z * di + bb.z, 0.f);
            v.w = fmaxf(a.w * di + bb.w, 0.f);
        }
        *reinterpret_cast<float4*>(&As[m][lk4]) = v;
        int k = lm + 16 * i;
        float4 w = *reinterpret_cast<const float4*>(W2 + (size_t)k * H + lk4);
        *reinterpret_cast<float4*>(&Ws[k][lk4]) = w;
    }
    __syncthreads();

    float acc[4][4];
#pragma unroll
    for (int i = 0; i < 4; i++)
#pragma unroll
        for (int j = 0; j < 4; j++) acc[i][j] = 0.f;

#pragma unroll 8
    for (int kk = 0; kk < 64; kk++) {
        float4 b4 = *reinterpret_cast<const float4*>(&Ws[kk][tx * 4]);
        float a0 = As[ty * 4 + 0][kk];
        float a1 = As[ty * 4 + 1][kk];
        float a2 = As[ty * 4 + 2][kk];
        float a3 = As[ty * 4 + 3][kk];
        acc[0][0] += a0 * b4.x; acc[0][1] += a0 * b4.y; acc[0][2] += a0 * b4.z; acc[0][3] += a0 * b4.w;
        acc[1][0] += a1 * b4.x; acc[1][1] += a1 * b4.y; acc[1][2] += a1 * b4.z; acc[1][3] += a1 * b4.w;
        acc[2][0] += a2 * b4.x; acc[2][1] += a2 * b4.y; acc[2][2] += a2 * b4.z; acc[2][3] += a2 * b4.w;
        acc[3][0] += a3 * b4.x; acc[3][1] += a3 * b4.y; acc[3][2] += a3 * b4.z; acc[3][3] += a3 * b4.w;
    }

#pragma unroll
    for (int i = 0; i < 4; i++) {
        int gm = m0 + ty * 4 + i;
        if (gm < N) {
            float di = g_dinv[gm];
            float4 r = make_float4(acc[i][0] * di, acc[i][1] * di, acc[i][2] * di, acc[i][3] * di);
            *reinterpret_cast<float4*>(&g_hs2[(size_t)gm * H + tx * 4]) = r;
            *reinterpret_cast<float4*>(&g_acc2[(size_t)gm * H + tx * 4]) = r;
        }
    }
}

// node MLP precompute: h2 = relu(acc2*dinv + b2)
// half=0: g_A = h2 @ Wm1[0:64] + bm1 ; half=1: g_B = h2 @ Wm1[64:128]
__global__ __launch_bounds__(256) void gemm3_tiled(
    const float* __restrict__ Wm1, const float* __restrict__ b2,
    const float* __restrict__ bm1, int N) {
    __shared__ float As[64][68];
    __shared__ float Ws[64][68];
    const int tx = threadIdx.x, ty = threadIdx.y;
    const int t = ty * 16 + tx;
    const int lm = t >> 4;
    const int lk4 = (t & 15) * 4;
    const int m0 = blockIdx.x * 64;
    const int half = blockIdx.y;

    float4 bb = *reinterpret_cast<const float4*>(b2 + lk4);
#pragma unroll
    for (int i = 0; i < 4; i++) {
        int m = lm + 16 * i;
        int gm = m0 + m;
        float4 v = make_float4(0.f, 0.f, 0.f, 0.f);
        if (gm < N) {
            float di = g_dinv[gm];
            float4 a = *reinterpret_cast<const float4*>(&g_acc2[(size_t)gm * H + lk4]);
            v.x = fmaxf(a.x * di + bb.x, 0.f);
            v.y = fmaxf(a.y * di + bb.y, 0.f);
            v.z = fmaxf(a.z * di + bb.z, 0.f);
            v.w = fmaxf(a.w * di + bb.w, 0.f);
        }
        *reinterpret_cast<float4*>(&As[m][lk4]) = v;
        int k = lm + 16 * i;
        float4 w = *reinterpret_cast<const float4*>(Wm1 + (size_t)(half * H + k) * H + lk4);
        *reinterpret_cast<float4*>(&Ws[k][lk4]) = w;
    }
    __syncthreads();

    float acc[4][4];
#pragma unroll
    for (int i = 0; i < 4; i++)
#pragma unroll
        for (int j = 0; j < 4; j++) acc[i][j] = 0.f;

#pragma unroll 8
    for (int kk = 0; kk < 64; kk++) {
        float4 b4 = *reinterpret_cast<const float4*>(&Ws[kk][tx * 4]);
        float a0 = As[ty * 4 + 0][kk];
        float a1 = As[ty * 4 + 1][kk];
        float a2 = As[ty * 4 + 2][kk];
        float a3 = As[ty * 4 + 3][kk];
        acc[0][0] += a0 * b4.x; acc[0][1] += a0 * b4.y; acc[0][2] += a0 * b4.z; acc[0][3] += a0 * b4.w;
        acc[1][0] += a1 * b4.x; acc[1][1] += a1 * b4.y; acc[1][2] += a1 * b4.z; acc[1][3] += a1 * b4.w;
        acc[2][0] += a2 * b4.x; acc[2][1] += a2 * b4.y; acc[2][2] += a2 * b4.z; acc[2][3] += a2 * b4.w;
        acc[3][0] += a3 * b4.x; acc[3][1] += a3 * b4.y; acc[3][2] += a3 * b4.z; acc[3][3] += a3 * b4.w;
    }

    float4 badd = make_float4(0.f, 0.f, 0.f, 0.f);
    if (half == 0) badd = *reinterpret_cast<const float4*>(bm1 + tx * 4);
    float* outbuf = (half == 0) ? g_A : g_B;
#pragma unroll
    for (int i = 0; i < 4; i++) {
        int gm = m0 + ty * 4 + i;
        if (gm < N) {
            float4 r = make_float4(acc[i][0] + badd.x, acc[i][1] + badd.y,
                                   acc[i][2] + badd.z, acc[i][3] + badd.w);
            *reinterpret_cast<float4*>(&outbuf[(size_t)gm * H + tx * 4]) = r;
        }
    }
}

// ---------------- scatter: acc[dst] += hs[src]  (16 threads/edge, red.v4)
__global__ void scatter_kernel(const int* __restrict__ src, const int* __restrict__ dst,
                               const float* __restrict__ hs, float* __restrict__ acc, int E) {
    int t = blockIdx.x * blockDim.x + threadIdx.x;
    int e = t >> 4;
    if (e >= E) return;
    int c = (t & 15) << 2;
    int s = src[e], d = dst[e];
    float4 v = *reinterpret_cast<const float4*>(hs + (size_t)s * H + c);
    float* p = acc + (size_t)d * H + c;
    asm volatile("red.global.add.v4.f32 [%0], {%1, %2, %3, %4};"
                 :: "l"(p), "f"(v.x), "f"(v.y), "f"(v.z), "f"(v.w) : "memory");
}

// ---------------- edge MLP (tiled): out[e] = relu(A[src]+B[dst]) @ Wm2 + bm2
// Block: 256 threads, 256 edges. Z staged transposed in smem: Zs[k][m].
#define EDGE_M 256
__global__ __launch_bounds__(256) void edge_tiled_kernel(
    const int* __restrict__ src, const int* __restrict__ dst,
    const float* __restrict__ Wm2, const float* __restrict__ bm2,
    float* __restrict__ out, int E) {
    __shared__ float Zs[H][EDGE_M + 8];   // [k][m]
    __shared__ float Ws[H][C_OUT];        // [k][c]
    __shared__ float bs[C_OUT];

    const int t = threadIdx.x;
    const int e0 = blockIdx.x * EDGE_M;

    // load weights + bias
    for (int i = t; i < H * C_OUT; i += 256) Ws[i / C_OUT][i % C_OUT] = Wm2[i];
    if (t < C_OUT) bs[t] = bm2[t];

    // stage Z: each thread handles one edge's full 64 features (transposed store)
    {
        int e = e0 + t;
        if (e < E) {
            int s = src[e], d = dst[e];
            const float4* Ap = reinterpret_cast<const float4*>(g_A + (size_t)s * H);
            const float4* Bp = reinterpret_cast<const float4*>(g_B + (size_t)d * H);
#pragma unroll
            for (int q = 0; q < H / 4; q++) {
                float4 a4 = Ap[q];
                float4 b4 = Bp[q];
                Zs[q * 4 + 0][t] = fmaxf(a4.x + b4.x, 0.f);
                Zs[q * 4 + 1][t] = fmaxf(a4.y + b4.y, 0.f);
                Zs[q * 4 + 2][t] = fmaxf(a4.z + b4.z, 0.f);
                Zs[q * 4 + 3][t] = fmaxf(a4.w + b4.w, 0.f);
            }
        } else {
#pragma unroll
            for (int k = 0; k < H; k++) Zs[k][t] = 0.f;
        }
    }
    __syncthreads();

    // compute: microtile 4 edges x 4 cols per thread
    const int cg = t & 3;          // col group: cols cg*4 .. cg*4+3
    const int mg = t >> 2;         // edge group: edges mg*4 .. mg*4+3
    const int m0 = mg * 4;
    const int c0 = cg * 4;

    float acc[4][4];
    float4 bb = *reinterpret_cast<const float4*>(&bs[c0]);
#pragma unroll
    for (int i = 0; i < 4; i++) { acc[i][0] = bb.x; acc[i][1] = bb.y; acc[i][2] = bb.z; acc[i][3] = bb.w; }

#pragma unroll 8
    for (int k = 0; k < H; k++) {
        float4 z4 = *reinterpret_cast<const float4*>(&Zs[k][m0]);
        float4 w4 = *reinterpret_cast<const float4*>(&Ws[k][c0]);
        acc[0][0] += z4.x * w4.x; acc[0][1] += z4.x * w4.y; acc[0][2] += z4.x * w4.z; acc[0][3] += z4.x * w4.w;
        acc[1][0] += z4.y * w4.x; acc[1][1] += z4.y * w4.y; acc[1][2] += z4.y * w4.z; acc[1][3] += z4.y * w4.w;
        acc[2][0] += z4.z * w4.x; acc[2][1] += z4.z * w4.y; acc[2][2] += z4.z * w4.z; acc[2][3] += z4.z * w4.w;
        acc[3][0] += z4.w * w4.x; acc[3][1] += z4.w * w4.y; acc[3][2] += z4.w * w4.z; acc[3][3] += z4.w * w4.w;
    }

#pragma unroll
    for (int i = 0; i < 4; i++) {
        int e = e0 + m0 + i;
        if (e < E) {
            *reinterpret_cast<float4*>(out + (size_t)e * C_OUT + c0) =
                make_float4(acc[i][0], acc[i][1], acc[i][2], acc[i][3]);
        }
    }
}

extern "C" void kernel_launch(void* const* d_in, const int* in_sizes, int n_in,
                              void* d_out, int out_size) {
    const float* x    = (const float*)d_in[0];
    const int*   ei   = (const int*)d_in[1];
    const float* W1   = (const float*)d_in[2];
    const float* b1   = (const float*)d_in[3];
    const float* W2   = (const float*)d_in[4];
    const float* b2   = (const float*)d_in[5];
    const float* Wm1  = (const float*)d_in[6];
    const float* bm1  = (const float*)d_in[7];
    const float* Wm2  = (const float*)d_in[8];
    const float* bm2  = (const float*)d_in[9];
    float* out = (float*)d_out;

    int N = in_sizes[0] / IN_F;
    int E = in_sizes[1] / 2;
    const int* src = ei;
    const int* dst = ei + E;

    int*   degi; cudaGetSymbolAddress((void**)&degi, g_degi);
    float* hs1;  cudaGetSymbolAddress((void**)&hs1,  g_hs1);
    float* acc1; cudaGetSymbolAddress((void**)&acc1, g_acc1);
    float* hs2;  cudaGetSymbolAddress((void**)&hs2,  g_hs2);
    float* acc2; cudaGetSymbolAddress((void**)&acc2, g_acc2);

    int blocks_m = (N + 63) / 64;

    // degrees
    cudaMemsetAsync(degi, 0, (size_t)N * sizeof(int));
    count_kernel<<<(E + 255) / 256, 256>>>(dst, E);

    // conv1 (dinv computed + persisted in epilogue)
    gemm1_tiled<<<blocks_m, dim3(16, 16)>>>(x, W1, N);
    {
        long long tot = (long long)E * 16;
        scatter_kernel<<<(int)((tot + 255) / 256), 256>>>(src, dst, hs1, acc1, E);
    }

    // conv2
    gemm2_tiled<<<blocks_m, dim3(16, 16)>>>(W2, b1, N);
    {
        long long tot = (long long)E * 16;
        scatter_kernel<<<(int)((tot + 255) / 256), 256>>>(src, dst, hs2, acc2, E);
    }

    // node-side MLP precompute
    gemm3_tiled<<<dim3(blocks_m, 2), dim3(16, 16)>>>(Wm1, b2, bm1, N);

    // edge MLP
    edge_tiled_kernel<<<(E + EDGE_M - 1) / EDGE_M, 256>>>(src, dst, Wm2, bm2, out, E);
}

// round 5
// speedup vs baseline: 1.4141x; 1.0154x over previous
#include <cuda_runtime.h>
#include <cuda_bf16.h>
#include <cstdint>

// Problem constants (dataset fixed: N=50000, E=800000, IN=128, H=64, C=16)
#define MAXN 50016
#define H 64
#define IN_F 128
#define C_OUT 16

// Scratch (device globals; 16B aligned)
__device__ __align__(16) int   g_degi[MAXN];
__device__ __align__(16) float g_dinv[MAXN];
__device__ __align__(16) float g_hs1[MAXN * H];
__device__ __align__(16) float g_acc1[MAXN * H];
__device__ __align__(16) float g_hs2[MAXN * H];
__device__ __align__(16) float g_acc2[MAXN * H];
__device__ __align__(16) float g_A[MAXN * H];
__device__ __align__(16) float g_B[MAXN * H];

// ---------------- degree count (int atomics; g_degi pre-zeroed by memset)
__global__ void count_kernel(const int* __restrict__ dst, int E) {
    int e = blockIdx.x * blockDim.x + threadIdx.x;
    if (e < E) atomicAdd(&g_degi[dst[e]], 1);
}

// =====================================================================
// Tiled GEMM kernels: M-tile=64, N-tile=64, 256 threads, 4x4 microtile
// =====================================================================

// conv1: hs1 = (x @ W1) * dinv ; acc1 = hs1 (self-loop seed); also writes g_dinv
__global__ __launch_bounds__(256) void gemm1_tiled(
    const float* __restrict__ x, const float* __restrict__ W1, int N) {
    __shared__ float As[64][68];
    __shared__ float Ws[64][68];
    const int tx = threadIdx.x, ty = threadIdx.y;
    const int t = ty * 16 + tx;
    const int lm = t >> 4;
    const int lk4 = (t & 15) * 4;
    const int m0 = blockIdx.x * 64;

    float acc[4][4];
#pragma unroll
    for (int i = 0; i < 4; i++)
#pragma unroll
        for (int j = 0; j < 4; j++) acc[i][j] = 0.f;

    for (int k0 = 0; k0 < IN_F; k0 += 64) {
        __syncthreads();
#pragma unroll
        for (int i = 0; i < 4; i++) {
            int m = lm + 16 * i;
            int gm = m0 + m;
            float4 v = make_float4(0.f, 0.f, 0.f, 0.f);
            if (gm < N) v = *reinterpret_cast<const float4*>(x + (size_t)gm * IN_F + k0 + lk4);
            *reinterpret_cast<float4*>(&As[m][lk4]) = v;
            int k = lm + 16 * i;
            float4 w = *reinterpret_cast<const float4*>(W1 + (size_t)(k0 + k) * H + lk4);
            *reinterpret_cast<float4*>(&Ws[k][lk4]) = w;
        }
        __syncthreads();
#pragma unroll 8
        for (int kk = 0; kk < 64; kk++) {
            float4 b4 = *reinterpret_cast<const float4*>(&Ws[kk][tx * 4]);
            float a0 = As[ty * 4 + 0][kk];
            float a1 = As[ty * 4 + 1][kk];
            float a2 = As[ty * 4 + 2][kk];
            float a3 = As[ty * 4 + 3][kk];
            acc[0][0] += a0 * b4.x; acc[0][1] += a0 * b4.y; acc[0][2] += a0 * b4.z; acc[0][3] += a0 * b4.w;
            acc[1][0] += a1 * b4.x; acc[1][1] += a1 * b4.y; acc[1][2] += a1 * b4.z; acc[1][3] += a1 * b4.w;
            acc[2][0] += a2 * b4.x; acc[2][1] += a2 * b4.y; acc[2][2] += a2 * b4.z; acc[2][3] += a2 * b4.w;
            acc[3][0] += a3 * b4.x; acc[3][1] += a3 * b4.y; acc[3][2] += a3 * b4.z; acc[3][3] += a3 * b4.w;
        }
    }

#pragma unroll
    for (int i = 0; i < 4; i++) {
        int gm = m0 + ty * 4 + i;
        if (gm < N) {
            float di = rsqrtf((float)(g_degi[gm] + 1));  // +1 self loop
            if (tx == 0) g_dinv[gm] = di;
            float4 r = make_float4(acc[i][0] * di, acc[i][1] * di, acc[i][2] * di, acc[i][3] * di);
            *reinterpret_cast<float4*>(&g_hs1[(size_t)gm * H + tx * 4]) = r;
            *reinterpret_cast<float4*>(&g_acc1[(size_t)gm * H + tx * 4]) = r;
        }
    }
}

// conv2: h1 = relu(acc1*dinv + b1); hs2 = (h1 @ W2) * dinv; acc2 = hs2 (K=64)
__global__ __launch_bounds__(256) void gemm2_tiled(
    const float* __restrict__ W2, const float* __restrict__ b1, int N) {
    __shared__ float As[64][68];
    __shared__ float Ws[64][68];
    const int tx = threadIdx.x, ty = threadIdx.y;
    const int t = ty * 16 + tx;
    const int lm = t >> 4;
    const int lk4 = (t & 15) * 4;
    const int m0 = blockIdx.x * 64;

    float4 bb = *reinterpret_cast<const float4*>(b1 + lk4);
#pragma unroll
    for (int i = 0; i < 4; i++) {
        int m = lm + 16 * i;
        int gm = m0 + m;
        float4 v = make_float4(0.f, 0.f, 0.f, 0.f);
        if (gm < N) {
            float di = g_dinv[gm];
            float4 a = *reinterpret_cast<const float4*>(&g_acc1[(size_t)gm * H + lk4]);
            v.x = fmaxf(a.x * di + bb.x, 0.f);
            v.y = fmaxf(a.y * di + bb.y, 0.f);
            v.z = fmaxf(a.z * di + bb.z, 0.f);
            v.w = fmaxf(a.w * di + bb.w, 0.f);
        }
        *reinterpret_cast<float4*>(&As[m][lk4]) = v;
        int k = lm + 16 * i;
        float4 w = *reinterpret_cast<const float4*>(W2 + (size_t)k * H + lk4);
        *reinterpret_cast<float4*>(&Ws[k][lk4]) = w;
    }
    __syncthreads();

    float acc[4][4];
#pragma unroll
    for (int i = 0; i < 4; i++)
#pragma unroll
        for (int j = 0; j < 4; j++) acc[i][j] = 0.f;

#pragma unroll 8
    for (int kk = 0; kk < 64; kk++) {
        float4 b4 = *reinterpret_cast<const float4*>(&Ws[kk][tx * 4]);
        float a0 = As[ty * 4 + 0][kk];
        float a1 = As[ty * 4 + 1][kk];
        float a2 = As[ty * 4 + 2][kk];
        float a3 = As[ty * 4 + 3][kk];
        acc[0][0] += a0 * b4.x; acc[0][1] += a0 * b4.y; acc[0][2] += a0 * b4.z; acc[0][3] += a0 * b4.w;
        acc[1][0] += a1 * b4.x; acc[1][1] += a1 * b4.y; acc[1][2] += a1 * b4.z; acc[1][3] += a1 * b4.w;
        acc[2][0] += a2 * b4.x; acc[2][1] += a2 * b4.y; acc[2][2] += a2 * b4.z; acc[2][3] += a2 * b4.w;
        acc[3][0] += a3 * b4.x; acc[3][1] += a3 * b4.y; acc[3][2] += a3 * b4.z; acc[3][3] += a3 * b4.w;
    }

#pragma unroll
    for (int i = 0; i < 4; i++) {
        int gm = m0 + ty * 4 + i;
        if (gm < N) {
            float di = g_dinv[gm];
            float4 r = make_float4(acc[i][0] * di, acc[i][1] * di, acc[i][2] * di, acc[i][3] * di);
            *reinterpret_cast<float4*>(&g_hs2[(size_t)gm * H + tx * 4]) = r;
            *reinterpret_cast<float4*>(&g_acc2[(size_t)gm * H + tx * 4]) = r;
        }
    }
}

// node MLP precompute: h2 = relu(acc2*dinv + b2)
// half=0: g_A = h2 @ Wm1[0:64] + bm1 ; half=1: g_B = h2 @ Wm1[64:128]
__global__ __launch_bounds__(256) void gemm3_tiled(
    const float* __restrict__ Wm1, const float* __restrict__ b2,
    const float* __restrict__ bm1, int N) {
    __shared__ float As[64][68];
    __shared__ float Ws[64][68];
    const int tx = threadIdx.x, ty = threadIdx.y;
    const int t = ty * 16 + tx;
    const int lm = t >> 4;
    const int lk4 = (t & 15) * 4;
    const int m0 = blockIdx.x * 64;
    const int half = blockIdx.y;

    float4 bb = *reinterpret_cast<const float4*>(b2 + lk4);
#pragma unroll
    for (int i = 0; i < 4; i++) {
        int m = lm + 16 * i;
        int gm = m0 + m;
        float4 v = make_float4(0.f, 0.f, 0.f, 0.f);
        if (gm < N) {
            float di = g_dinv[gm];
            float4 a = *reinterpret_cast<const float4*>(&g_acc2[(size_t)gm * H + lk4]);
            v.x = fmaxf(a.x * di + bb.x, 0.f);
            v.y = fmaxf(a.y * di + bb.y, 0.f);
            v.z = fmaxf(a.z * di + bb.z, 0.f);
            v.w = fmaxf(a.w * di + bb.w, 0.f);
        }
        *reinterpret_cast<float4*>(&As[m][lk4]) = v;
        int k = lm + 16 * i;
        float4 w = *reinterpret_cast<const float4*>(Wm1 + (size_t)(half * H + k) * H + lk4);
        *reinterpret_cast<float4*>(&Ws[k][lk4]) = w;
    }
    __syncthreads();

    float acc[4][4];
#pragma unroll
    for (int i = 0; i < 4; i++)
#pragma unroll
        for (int j = 0; j < 4; j++) acc[i][j] = 0.f;

#pragma unroll 8
    for (int kk = 0; kk < 64; kk++) {
        float4 b4 = *reinterpret_cast<const float4*>(&Ws[kk][tx * 4]);
        float a0 = As[ty * 4 + 0][kk];
        float a1 = As[ty * 4 + 1][kk];
        float a2 = As[ty * 4 + 2][kk];
        float a3 = As[ty * 4 + 3][kk];
        acc[0][0] += a0 * b4.x; acc[0][1] += a0 * b4.y; acc[0][2] += a0 * b4.z; acc[0][3] += a0 * b4.w;
        acc[1][0] += a1 * b4.x; acc[1][1] += a1 * b4.y; acc[1][2] += a1 * b4.z; acc[1][3] += a1 * b4.w;
        acc[2][0] += a2 * b4.x; acc[2][1] += a2 * b4.y; acc[2][2] += a2 * b4.z; acc[2][3] += a2 * b4.w;
        acc[3][0] += a3 * b4.x; acc[3][1] += a3 * b4.y; acc[3][2] += a3 * b4.z; acc[3][3] += a3 * b4.w;
    }

    float4 badd = make_float4(0.f, 0.f, 0.f, 0.f);
    if (half == 0) badd = *reinterpret_cast<const float4*>(bm1 + tx * 4);
    float* outbuf = (half == 0) ? g_A : g_B;
#pragma unroll
    for (int i = 0; i < 4; i++) {
        int gm = m0 + ty * 4 + i;
        if (gm < N) {
            float4 r = make_float4(acc[i][0] + badd.x, acc[i][1] + badd.y,
                                   acc[i][2] + badd.z, acc[i][3] + badd.w);
            *reinterpret_cast<float4*>(&outbuf[(size_t)gm * H + tx * 4]) = r;
        }
    }
}

// ---------------- scatter: acc[dst] += hs[src]  (8 threads/edge, 2x red.v4)
__global__ void scatter_kernel(const int* __restrict__ src, const int* __restrict__ dst,
                               const float* __restrict__ hs, float* __restrict__ acc, int E) {
    int t = blockIdx.x * blockDim.x + threadIdx.x;
    int e = t >> 3;
    if (e >= E) return;
    int c = (t & 7) << 3;  // 0,8,...,56
    int s = src[e], d = dst[e];
    const float4* hp = reinterpret_cast<const float4*>(hs + (size_t)s * H + c);
    float4 v0 = hp[0];
    float4 v1 = hp[1];
    float* p = acc + (size_t)d * H + c;
    asm volatile("red.global.add.v4.f32 [%0], {%1, %2, %3, %4};"
                 :: "l"(p), "f"(v0.x), "f"(v0.y), "f"(v0.z), "f"(v0.w) : "memory");
    asm volatile("red.global.add.v4.f32 [%0], {%1, %2, %3, %4};"
                 :: "l"(p + 4), "f"(v1.x), "f"(v1.y), "f"(v1.z), "f"(v1.w) : "memory");
}

// ---------------- edge MLP: out[e] = relu(A[src]+B[dst]) @ Wm2 + bm2 (R2 version)
__global__ void edge_kernel(const int* __restrict__ src, const int* __restrict__ dst,
                            const float* __restrict__ Wm2, const float* __restrict__ bm2,
                            float* __restrict__ out, int E) {
    __shared__ float Ws[H * C_OUT];
    __shared__ float bs[C_OUT];
    int tid = threadIdx.x;
    for (int i = tid; i < H * C_OUT; i += blockDim.x) Ws[i] = Wm2[i];
    if (tid < C_OUT) bs[tid] = bm2[tid];
    __syncthreads();

    int e = blockIdx.x * blockDim.x + tid;
    if (e >= E) return;
    int s = src[e], d = dst[e];
    const float4* Ap = reinterpret_cast<const float4*>(g_A + (size_t)s * H);
    const float4* Bp = reinterpret_cast<const float4*>(g_B + (size_t)d * H);

    float acc[C_OUT];
#pragma unroll
    for (int c = 0; c < C_OUT; c++) acc[c] = bs[c];

#pragma unroll
    for (int q = 0; q < H / 4; q++) {
        float4 a4 = Ap[q];
        float4 b4 = Bp[q];
        float z0 = fmaxf(a4.x + b4.x, 0.f);
        float z1 = fmaxf(a4.y + b4.y, 0.f);
        float z2 = fmaxf(a4.z + b4.z, 0.f);
        float z3 = fmaxf(a4.w + b4.w, 0.f);
        int k = q * 4;
        const float4* w0 = reinterpret_cast<const float4*>(Ws + (k + 0) * C_OUT);
        const float4* w1 = reinterpret_cast<const float4*>(Ws + (k + 1) * C_OUT);
        const float4* w2 = reinterpret_cast<const float4*>(Ws + (k + 2) * C_OUT);
        const float4* w3 = reinterpret_cast<const float4*>(Ws + (k + 3) * C_OUT);
#pragma unroll
        for (int cq = 0; cq < 4; cq++) {
            float4 r0 = w0[cq], r1 = w1[cq], r2 = w2[cq], r3 = w3[cq];
            acc[cq * 4 + 0] += z0 * r0.x + z1 * r1.x + z2 * r2.x + z3 * r3.x;
            acc[cq * 4 + 1] += z0 * r0.y + z1 * r1.y + z2 * r2.y + z3 * r3.y;
            acc[cq * 4 + 2] += z0 * r0.z + z1 * r1.z + z2 * r2.z + z3 * r3.z;
            acc[cq * 4 + 3] += z0 * r0.w + z1 * r1.w + z2 * r2.w + z3 * r3.w;
        }
    }

    float4* op = reinterpret_cast<float4*>(out + (size_t)e * C_OUT);
#pragma unroll
    for (int c = 0; c < 4; c++)
        op[c] = make_float4(acc[c * 4 + 0], acc[c * 4 + 1], acc[c * 4 + 2], acc[c * 4 + 3]);
}

extern "C" void kernel_launch(void* const* d_in, const int* in_sizes, int n_in,
                              void* d_out, int out_size) {
    const float* x    = (const float*)d_in[0];
    const int*   ei   = (const int*)d_in[1];
    const float* W1   = (const float*)d_in[2];
    const float* b1   = (const float*)d_in[3];
    const float* W2   = (const float*)d_in[4];
    const float* b2   = (const float*)d_in[5];
    const float* Wm1  = (const float*)d_in[6];
    const float* bm1  = (const float*)d_in[7];
    const float* Wm2  = (const float*)d_in[8];
    const float* bm2  = (const float*)d_in[9];
    float* out = (float*)d_out;

    int N = in_sizes[0] / IN_F;
    int E = in_sizes[1] / 2;
    const int* src = ei;
    const int* dst = ei + E;

    int*   degi; cudaGetSymbolAddress((void**)&degi, g_degi);
    float* hs1;  cudaGetSymbolAddress((void**)&hs1,  g_hs1);
    float* acc1; cudaGetSymbolAddress((void**)&acc1, g_acc1);
    float* hs2;  cudaGetSymbolAddress((void**)&hs2,  g_hs2);
    float* acc2; cudaGetSymbolAddress((void**)&acc2, g_acc2);

    int blocks_m = (N + 63) / 64;

    // degrees
    cudaMemsetAsync(degi, 0, (size_t)N * sizeof(int));
    count_kernel<<<(E + 255) / 256, 256>>>(dst, E);

    // conv1 (dinv computed + persisted in epilogue)
    gemm1_tiled<<<blocks_m, dim3(16, 16)>>>(x, W1, N);
    {
        long long tot = (long long)E * 8;
        scatter_kernel<<<(int)((tot + 255) / 256), 256>>>(src, dst, hs1, acc1, E);
    }

    // conv2
    gemm2_tiled<<<blocks_m, dim3(16, 16)>>>(W2, b1, N);
    {
        long long tot = (long long)E * 8;
        scatter_kernel<<<(int)((tot + 255) / 256), 256>>>(src, dst, hs2, acc2, E);
    }

    // node-side MLP precompute
    gemm3_tiled<<<dim3(blocks_m, 2), dim3(16, 16)>>>(Wm1, b2, bm1, N);

    // edge MLP
    edge_kernel<<<(E + 255) / 256, 256>>>(src, dst, Wm2, bm2, out, E);
}